// round 5
// baseline (speedup 1.0000x reference)
#include <cuda_runtime.h>
#include <cstdint>

#define WIRE_DIM   32
#define NUM_WIRES  64
#define ROW_ELEMS  (NUM_WIRES * WIRE_DIM)   // 2048 floats per batch row
#define WPB        2                        // warps per block
#define ITERS      4                        // rows per warp (pipelined)
#define NTHREADS   (WPB * 32)
#define RPB        (WPB * ITERS)            // 8 rows per block

typedef unsigned long long u64;

// ---- packed f32x2 helpers (Blackwell FFMA2 via PTX) ----
__device__ __forceinline__ u64 pack2(float v) {
    u64 r; asm("mov.b64 %0, {%1, %1};" : "=l"(r) : "f"(v)); return r;
}
__device__ __forceinline__ u64 pack2f(float lo, float hi) {
    u64 r; asm("mov.b64 %0, {%1, %2};" : "=l"(r) : "f"(lo), "f"(hi)); return r;
}
__device__ __forceinline__ void ffma2(u64 &d, u64 a, u64 b) {
    asm("fma.rn.f32x2 %0, %1, %2, %0;" : "+l"(d) : "l"(a), "l"(b));
}
__device__ __forceinline__ float2 unpack2(u64 v) {
    float2 f; asm("mov.b64 {%0, %1}, %2;" : "=f"(f.x), "=f"(f.y) : "l"(v)); return f;
}
__device__ __forceinline__ float selk(float4 v, int k) {
    return (k == 0) ? v.x : (k == 1) ? v.y : (k == 2) ? v.z : v.w;
}

// ---- cp.async (LDGSTS) helpers ----
__device__ __forceinline__ void cp16(uint32_t dst_smem, const float* src) {
    asm volatile("cp.async.cg.shared.global [%0], [%1], 16;" :: "r"(dst_smem), "l"(src));
}
__device__ __forceinline__ void cp_commit() {
    asm volatile("cp.async.commit_group;");
}
template <int N> __device__ __forceinline__ void cp_wait() {
    asm volatile("cp.async.wait_group %0;" :: "n"(N));
}

__global__ __launch_bounds__(NTHREADS)
void trainer_kernel(const float* __restrict__ outputs,
                    const int* __restrict__ tests_i32,
                    const float* __restrict__ W1,
                    const float* __restrict__ b1,
                    const float* __restrict__ W2,
                    const float* __restrict__ b2,
                    float* __restrict__ out,
                    int B)
{
    __shared__ __align__(16) float sW1[64 * 12];          // stride-12 padded rows
    __shared__ __align__(16) float sb1[12];
    __shared__ __align__(16) float sW2[12];
    __shared__ __align__(16) float sx[WPB][2][ROW_ELEMS]; // 2-stage buffer per warp, 32 KB

    const int tid  = threadIdx.x;
    const int warp = tid >> 5;
    const int lane = tid & 31;

    // --- weights -> smem (block-cooperative, once) ---
    #pragma unroll
    for (int i = tid; i < 640; i += NTHREADS) {
        int r = i / 10, h = i - r * 10;
        sW1[r * 12 + h] = W1[i];
    }
    if (tid < 10) { sb1[tid] = b1[tid]; sW2[tid] = W2[tid]; }

    // --- detect tests dtype (int64 pairs have zero high-words at odd slots) ---
    int hv = tests_i32[2 * lane + 1];
    #pragma unroll
    for (int o = 16; o > 0; o >>= 1) hv |= __shfl_xor_sync(0xffffffffu, hv, o);
    const bool is_i64 = (hv == 0);

    __syncthreads();   // weights visible; no block sync after this point

    const int rbase = (blockIdx.x * WPB + warp) * ITERS;
    const uint32_t sbuf0 = (uint32_t)__cvta_generic_to_shared(&sx[warp][0][0]);
    const uint32_t sbuf1 = (uint32_t)__cvta_generic_to_shared(&sx[warp][1][0]);

    // stage one row: coalesced 16B cp.async -> chunk-rotated smem scatter
    auto stage_row = [&](int r, uint32_t sb) {
        const float* src = outputs + (size_t)r * ROW_ELEMS;
        #pragma unroll
        for (int t = 0; t < 16; t++) {
            int f = t * 32 + lane;          // float4 index 0..511
            int w = f >> 3;                 // wire
            int c = f & 7;                  // chunk within wire
            int off = w * 32 + (((c + w) & 7) << 2);   // floats
            cp16(sb + (uint32_t)(off << 2), src + (f << 2));
        }
    };

    if (rbase < B) stage_row(rbase, sbuf0);
    cp_commit();

    #pragma unroll
    for (int i = 0; i < ITERS; i++) {
        const int r = rbase + i;

        if (i + 1 < ITERS) {                 // prefetch next row into other buffer
            if (r + 1 < B) stage_row(r + 1, (i & 1) ? sbuf0 : sbuf1);
            cp_commit();
            cp_wait<1>();
        } else {
            cp_wait<0>();
        }
        __syncwarp();
        if (r >= B) break;

        const float* xr = sx[warp][i & 1];

        // --- test indices (warp-uniform broadcast loads) ---
        int person, loc;
        if (is_i64) { person = tests_i32[4 * r]; loc = tests_i32[4 * r + 2]; }
        else        { person = tests_i32[2 * r]; loc = tests_i32[2 * r + 1]; }
        person &= 63;

        // --- person contribution: lanes 0..9 compute pc[h], then shuffle-broadcast ---
        float pcv = 0.f;
        if (lane < 10) {
            const float* px = &xr[person * 32];
            float pc = sb1[lane];
            #pragma unroll
            for (int c = 0; c < 8; c++) {
                float4 v = *(const float4*)&px[(((c + person) & 7) << 2)];
                const int d = c * 4;
                pc += v.x * sW1[(d + 0) * 12 + lane];
                pc += v.y * sW1[(d + 1) * 12 + lane];
                pc += v.z * sW1[(d + 2) * 12 + lane];
                pc += v.w * sW1[(d + 3) * 12 + lane];
            }
            pcv = pc;
        }

        u64 accA[5], accB[5];
        #pragma unroll
        for (int h = 0; h < 5; h++) {
            float lo = __shfl_sync(0xffffffffu, pcv, 2 * h);
            float hi = __shfl_sync(0xffffffffu, pcv, 2 * h + 1);
            u64 p = pack2f(lo, hi);
            accA[h] = p; accB[h] = p;
        }

        // --- main MLP: lane handles wires lane and lane+32 (conflict-free LDS.128) ---
        const int bA = lane * 32;
        const int bB = (lane + 32) * 32;

        #pragma unroll
        for (int c = 0; c < 8; c++) {
            const int rot = ((c + lane) & 7) << 2;
            float4 vA = *(const float4*)&xr[bA + rot];
            float4 vB = *(const float4*)&xr[bB + rot];
            const float* wr = &sW1[(32 + c * 4) * 12];

            #pragma unroll
            for (int k = 0; k < 4; k++) {
                const float* wrow = wr + k * 12;
                ulonglong2 w01 = *(const ulonglong2*)(wrow);      // LDS.128 broadcast
                ulonglong2 w23 = *(const ulonglong2*)(wrow + 4);  // LDS.128 broadcast
                u64        w4  = *(const u64*)(wrow + 8);         // LDS.64  broadcast
                u64 av = pack2(selk(vA, k));
                u64 bv = pack2(selk(vB, k));
                ffma2(accA[0], av, w01.x); ffma2(accB[0], bv, w01.x);
                ffma2(accA[1], av, w01.y); ffma2(accB[1], bv, w01.y);
                ffma2(accA[2], av, w23.x); ffma2(accB[2], bv, w23.x);
                ffma2(accA[3], av, w23.y); ffma2(accB[3], bv, w23.y);
                ffma2(accA[4], av, w4);    ffma2(accB[4], bv, w4);
            }
        }

        // --- relu + output layer -> two logits per lane ---
        const float b2v = __ldg(b2);
        float la = b2v, lb = b2v;
        #pragma unroll
        for (int h = 0; h < 5; h++) {
            float w0 = sW2[2 * h], w1 = sW2[2 * h + 1];
            float2 f;
            f = unpack2(accA[h]); la += fmaxf(f.x, 0.f) * w0 + fmaxf(f.y, 0.f) * w1;
            f = unpack2(accB[h]); lb += fmaxf(f.x, 0.f) * w0 + fmaxf(f.y, 0.f) * w1;
        }

        // --- warp log-softmax over 64 logits, pick location ---
        float m = fmaxf(la, lb);
        #pragma unroll
        for (int o = 16; o > 0; o >>= 1)
            m = fmaxf(m, __shfl_xor_sync(0xffffffffu, m, o));
        float s = __expf(la - m) + __expf(lb - m);
        #pragma unroll
        for (int o = 16; o > 0; o >>= 1)
            s += __shfl_xor_sync(0xffffffffu, s, o);

        // wire w -> lane (w & 31), slot (w >> 5); loc warp-uniform
        float cand = (loc >> 5) ? lb : la;
        cand = __shfl_sync(0xffffffffu, cand, loc & 31);

        if (lane == 0) out[r] = -(cand - m - __logf(s));
    }
}

extern "C" void kernel_launch(void* const* d_in, const int* in_sizes, int n_in,
                              void* d_out, int out_size)
{
    const float* outputs = (const float*)d_in[0];
    const int*   tests   = (const int*)d_in[1];
    const float* W1      = (const float*)d_in[2];
    const float* b1      = (const float*)d_in[3];
    const float* W2      = (const float*)d_in[4];
    const float* b2      = (const float*)d_in[5];
    float* out = (float*)d_out;
    int B = out_size;

    int blocks = (B + RPB - 1) / RPB;
    trainer_kernel<<<blocks, NTHREADS>>>(outputs, tests, W1, b1, W2, b2, out, B);
}

// round 7
// speedup vs baseline: 1.0504x; 1.0504x over previous
#include <cuda_runtime.h>
#include <cstdint>

#define WIRE_DIM   32
#define NUM_WIRES  64
#define ROW_ELEMS  (NUM_WIRES * WIRE_DIM)   // 2048 floats per batch row
#define WPB        2                        // warps per block
#define ITERS      4                        // rows per warp (pipelined ring)
#define NTHREADS   (WPB * 32)
#define RPB        (WPB * ITERS)            // 8 rows per block

typedef unsigned long long u64;

// ---- packed f32x2 helpers ----
__device__ __forceinline__ u64 pack2f(float lo, float hi) {
    u64 r; asm("mov.b64 %0, {%1, %2};" : "=l"(r) : "f"(lo), "f"(hi)); return r;
}
__device__ __forceinline__ void ffma2(u64 &d, u64 a, u64 b) {
    asm("fma.rn.f32x2 %0, %1, %2, %0;" : "+l"(d) : "l"(a), "l"(b));
}
__device__ __forceinline__ float2 unpack2(u64 v) {
    float2 f; asm("mov.b64 {%0, %1}, %2;" : "=f"(f.x), "=f"(f.y) : "l"(v)); return f;
}

// ---- cp.async (LDGSTS) helpers ----
__device__ __forceinline__ void cp16(uint32_t dst_smem, const float* src) {
    asm volatile("cp.async.cg.shared.global [%0], [%1], 16;" :: "r"(dst_smem), "l"(src));
}
__device__ __forceinline__ void cp_commit() { asm volatile("cp.async.commit_group;"); }
template <int N> __device__ __forceinline__ void cp_wait() {
    asm volatile("cp.async.wait_group %0;" :: "n"(N));
}

__global__ __launch_bounds__(NTHREADS)
void trainer_kernel(const float* __restrict__ outputs,
                    const int* __restrict__ tests_i32,
                    const float* __restrict__ W1,
                    const float* __restrict__ b1,
                    const float* __restrict__ W2,
                    const float* __restrict__ b2,
                    float* __restrict__ out,
                    int B)
{
    // paired weights: sWt[p*10+h] = (W1[2p][h], W1[2p+1][h]), p=0..31
    __shared__ __align__(16) u64   sWt[320];            // 2560 B
    __shared__ __align__(16) float sb1[12];
    __shared__ __align__(16) float sW2[12];
    __shared__ __align__(16) float sx[WPB][2][ROW_ELEMS];  // 32 KB ring

    const int tid  = threadIdx.x;
    const int warp = tid >> 5;
    const int lane = tid & 31;

    // --- build paired-transposed weights (block-cooperative, once) ---
    #pragma unroll
    for (int i = tid; i < 320; i += NTHREADS) {
        int p = i / 10, h = i - 10 * p;
        sWt[i] = pack2f(W1[(2 * p) * 10 + h], W1[(2 * p + 1) * 10 + h]);
    }
    if (tid < 10) { sb1[tid] = b1[tid]; sW2[tid] = W2[tid]; }

    // --- detect tests dtype (int64 pairs have zero high-words at odd slots) ---
    int hvv = tests_i32[2 * lane + 1];
    #pragma unroll
    for (int o = 16; o > 0; o >>= 1) hvv |= __shfl_xor_sync(0xffffffffu, hvv, o);
    const bool is_i64 = (hvv == 0);

    __syncthreads();

    const int rbase = (blockIdx.x * WPB + warp) * ITERS;
    const uint32_t sbuf[2] = {
        (uint32_t)__cvta_generic_to_shared(&sx[warp][0][0]),
        (uint32_t)__cvta_generic_to_shared(&sx[warp][1][0])
    };

    // stage one row: coalesced 16B cp.async -> chunk-rotated smem scatter
    auto stage_row = [&](int r, uint32_t sb) {
        const float* src = outputs + (size_t)r * ROW_ELEMS;
        #pragma unroll
        for (int t = 0; t < 16; t++) {
            int f = t * 32 + lane;
            int w = f >> 3;
            int c = f & 7;
            int off = w * 32 + (((c + w) & 7) << 2);
            cp16(sb + (uint32_t)(off << 2), src + (f << 2));
        }
    };

    if (rbase < B) stage_row(rbase, sbuf[0]);
    cp_commit();

    const float b2v = __ldg(b2);

    #pragma unroll
    for (int i = 0; i < ITERS; i++) {
        const int r = rbase + i;

        if (i + 1 < ITERS) {
            if (r + 1 < B) stage_row(r + 1, sbuf[(i + 1) & 1]);
            cp_commit();
            cp_wait<1>();
        } else {
            cp_wait<0>();
        }
        __syncwarp();
        if (r >= B) break;

        const float* xr = sx[warp][i & 1];

        // --- test indices (warp-uniform) ---
        int person, loc;
        if (is_i64) { person = tests_i32[4 * r]; loc = tests_i32[4 * r + 2]; }
        else        { person = tests_i32[2 * r]; loc = tests_i32[2 * r + 1]; }
        person &= 63;

        // --- person contribution via paired weights (branchless, h = lane clamped) ---
        const int hh = (lane < 10) ? lane : 0;
        u64 pcacc = pack2f(sb1[hh], 0.f);
        const float* px = &xr[person * 32];
        #pragma unroll
        for (int c = 0; c < 8; c++) {
            // broadcast LDS.128 -> two d-pairs directly as u64
            ulonglong2 pv = *(const ulonglong2*)&px[(((c + person) & 7) << 2)];
            ffma2(pcacc, pv.x, sWt[(2 * c) * 10 + hh]);
            ffma2(pcacc, pv.y, sWt[(2 * c + 1) * 10 + hh]);
        }
        float2 pcp2 = unpack2(pcacc);
        float pcv = pcp2.x + pcp2.y;

        // --- init accumulators: acc[h] = (pc[h], 0), for wires lane and lane+32 ---
        u64 accA[10], accB[10];
        #pragma unroll
        for (int h = 0; h < 10; h++) {
            u64 p = pack2f(__shfl_sync(0xffffffffu, pcv, h), 0.f);
            accA[h] = p; accB[h] = p;
        }

        // --- main MLP: per chunk, 2 x-LDS.128 + 10 w-LDS.128 + 40 FFMA2, zero packs ---
        const int bA = lane * 32;
        const int bB = (lane + 32) * 32;

        #pragma unroll
        for (int c = 0; c < 8; c++) {
            const int rot = ((c + lane) & 7) << 2;
            ulonglong2 xa = *(const ulonglong2*)&xr[bA + rot];   // d-pairs 2c, 2c+1
            ulonglong2 xb = *(const ulonglong2*)&xr[bB + rot];

            #pragma unroll
            for (int pp = 0; pp < 2; pp++) {
                const u64* wb = &sWt[(16 + 2 * c + pp) * 10];
                ulonglong2 w01 = *(const ulonglong2*)(wb);
                ulonglong2 w23 = *(const ulonglong2*)(wb + 2);
                ulonglong2 w45 = *(const ulonglong2*)(wb + 4);
                ulonglong2 w67 = *(const ulonglong2*)(wb + 6);
                ulonglong2 w89 = *(const ulonglong2*)(wb + 8);
                u64 xav = pp ? xa.y : xa.x;
                u64 xbv = pp ? xb.y : xb.x;
                ffma2(accA[0], xav, w01.x); ffma2(accB[0], xbv, w01.x);
                ffma2(accA[1], xav, w01.y); ffma2(accB[1], xbv, w01.y);
                ffma2(accA[2], xav, w23.x); ffma2(accB[2], xbv, w23.x);
                ffma2(accA[3], xav, w23.y); ffma2(accB[3], xbv, w23.y);
                ffma2(accA[4], xav, w45.x); ffma2(accB[4], xbv, w45.x);
                ffma2(accA[5], xav, w45.y); ffma2(accB[5], xbv, w45.y);
                ffma2(accA[6], xav, w67.x); ffma2(accB[6], xbv, w67.x);
                ffma2(accA[7], xav, w67.y); ffma2(accB[7], xbv, w67.y);
                ffma2(accA[8], xav, w89.x); ffma2(accB[8], xbv, w89.x);
                ffma2(accA[9], xav, w89.y); ffma2(accB[9], xbv, w89.y);
            }
        }

        // --- relu + output layer -> two logits per lane ---
        float la = b2v, lb = b2v;
        #pragma unroll
        for (int h = 0; h < 10; h++) {
            float w2h = sW2[h];
            float2 fa = unpack2(accA[h]);
            float2 fb = unpack2(accB[h]);
            la += fmaxf(fa.x + fa.y, 0.f) * w2h;
            lb += fmaxf(fb.x + fb.y, 0.f) * w2h;
        }

        // --- warp log-softmax over 64 logits, pick location ---
        float m = fmaxf(la, lb);
        #pragma unroll
        for (int o = 16; o > 0; o >>= 1)
            m = fmaxf(m, __shfl_xor_sync(0xffffffffu, m, o));
        float s = __expf(la - m) + __expf(lb - m);
        #pragma unroll
        for (int o = 16; o > 0; o >>= 1)
            s += __shfl_xor_sync(0xffffffffu, s, o);

        float cand = (loc >> 5) ? lb : la;       // wire w -> lane (w&31), slot (w>>5)
        cand = __shfl_sync(0xffffffffu, cand, loc & 31);

        if (lane == 0) out[r] = -(cand - m - __logf(s));
    }
}

extern "C" void kernel_launch(void* const* d_in, const int* in_sizes, int n_in,
                              void* d_out, int out_size)
{
    const float* outputs = (const float*)d_in[0];
    const int*   tests   = (const int*)d_in[1];
    const float* W1      = (const float*)d_in[2];
    const float* b1      = (const float*)d_in[3];
    const float* W2      = (const float*)d_in[4];
    const float* b2      = (const float*)d_in[5];
    float* out = (float*)d_out;
    int B = out_size;

    int blocks = (B + RPB - 1) / RPB;
    trainer_kernel<<<blocks, NTHREADS>>>(outputs, tests, W1, b1, W2, b2, out, B);
}